// round 11
// baseline (speedup 1.0000x reference)
#include <cuda_runtime.h>
#include <cuda_fp16.h>
#include <mma.h>

#define N_NODES 50000
#define N_EDGES 600000
#define IN_FEATS 16
#define H 128
#define N_CLASSES 4
#define N_HIDDEN 19

#define SCAN_NB ((N_NODES + 1023) / 1024)   // 49 blocks of 1024

using namespace nvcuda;

// ---------------- scratch (device globals; no allocation allowed) ----------------
__device__ __half g_bufA[N_NODES * H];          // fp16 h (agg output / GEMM input)
__device__ __half g_bufZ[N_NODES * H];          // fp16 z (GEMM output / agg gather src)
__device__ __half g_Wh16[N_HIDDEN * H * H];     // fp16 hidden weights
__device__ int    g_deg[N_NODES];
__device__ int    g_cnt[N_NODES];
__device__ int    g_row_ptr[N_NODES + 1];
__device__ float  g_deg_inv[N_NODES];
__device__ int    g_bsum[SCAN_NB];
__device__ int    g_boff[SCAN_NB];
__device__ int2   g_csr[N_EDGES];               // {src, float_as_int(w)} per edge

// ---------------- preprocessing ----------------
__global__ void zero_counts_kernel() {
    int i = blockIdx.x * blockDim.x + threadIdx.x;
    if (i < N_NODES) { g_deg[i] = 0; g_cnt[i] = 0; }
}

__global__ void hist_kernel(const int* __restrict__ dst) {
    int i = blockIdx.x * blockDim.x + threadIdx.x;
    if (i < N_EDGES) atomicAdd(&g_deg[dst[i]], 1);
}

__global__ void convert_w_kernel(const float* __restrict__ W) {
    int i = blockIdx.x * blockDim.x + threadIdx.x;     // one float4 -> one uint2(half4)
    if (i < N_HIDDEN * H * H / 4) {
        float4 v = __ldg(reinterpret_cast<const float4*>(W) + i);
        uint2 o;
        *(__half2*)&o.x = __float22half2_rn(make_float2(v.x, v.y));
        *(__half2*)&o.y = __float22half2_rn(make_float2(v.z, v.w));
        reinterpret_cast<uint2*>(g_Wh16)[i] = o;
    }
}

// ---- 3-phase parallel exclusive scan of g_deg -> g_row_ptr ----
__global__ void __launch_bounds__(1024) scan1_kernel() {
    __shared__ int wsum[32];
    int tid = threadIdx.x;
    int i = blockIdx.x * 1024 + tid;
    int lane = tid & 31, wid = tid >> 5;
    int d = (i < N_NODES) ? g_deg[i] : 0;
    // warp inclusive scan
    int x = d;
#pragma unroll
    for (int off = 1; off < 32; off <<= 1) {
        int t = __shfl_up_sync(0xffffffffu, x, off);
        if (lane >= off) x += t;
    }
    if (lane == 31) wsum[wid] = x;
    __syncthreads();
    if (wid == 0) {
        int s = wsum[lane];
#pragma unroll
        for (int off = 1; off < 32; off <<= 1) {
            int t = __shfl_up_sync(0xffffffffu, s, off);
            if (lane >= off) s += t;
        }
        wsum[lane] = s;
    }
    __syncthreads();
    int base = (wid == 0) ? 0 : wsum[wid - 1];
    int incl = base + x;
    if (i < N_NODES) {
        g_row_ptr[i] = incl - d;                       // block-local exclusive prefix
        g_deg_inv[i] = 1.0f / fmaxf((float)d, 1.0f);
    }
    if (tid == 1023) g_bsum[blockIdx.x] = incl;        // block total
}

__global__ void scan2_kernel() {
    __shared__ int s[64];
    int tid = threadIdx.x;
    s[tid] = (tid < SCAN_NB) ? g_bsum[tid] : 0;
    __syncthreads();
    for (int off = 1; off < 64; off <<= 1) {
        int t = (tid >= off) ? s[tid - off] : 0;
        __syncthreads();
        s[tid] += t;
        __syncthreads();
    }
    if (tid < SCAN_NB) g_boff[tid] = (tid == 0) ? 0 : s[tid - 1];
    if (tid == 63) g_row_ptr[N_NODES] = s[SCAN_NB - 1];
}

__global__ void scan3_kernel() {
    int i = blockIdx.x * blockDim.x + threadIdx.x;
    if (i < N_NODES) g_row_ptr[i] += g_boff[i >> 10];
}

__global__ void fill_kernel(const int* __restrict__ src, const int* __restrict__ dst,
                            const float* __restrict__ ew) {
    int i = blockIdx.x * blockDim.x + threadIdx.x;
    if (i < N_EDGES) {
        int d = dst[i];
        int pos = g_row_ptr[d] + atomicAdd(&g_cnt[d], 1);
        g_csr[pos] = make_int2(src[i], __float_as_int(ew[i]));
    }
}

// ---------------- layer-0 GEMM (fp32 in, FFMA2, fp16 out): K=16 ----------------
template<int K>
__global__ void __launch_bounds__(256)
gemm_bias_kernel(const float* __restrict__ A, const float* __restrict__ W,
                 const float* __restrict__ bias, __half2* __restrict__ Z, int M)
{
    const int BK = 16;
    __shared__ float As[BK][H + 1];
    __shared__ float Ws[BK][H];
    int tid = threadIdx.x;
    int tx = tid & 15;
    int ty = tid >> 4;
    int m0 = blockIdx.x * H;

    unsigned long long acc[8][4];
#pragma unroll
    for (int r = 0; r < 8; r++)
#pragma unroll
        for (int c = 0; c < 4; c++) acc[r][c] = 0ull;

    for (int k0 = 0; k0 < K; k0 += BK) {
#pragma unroll
        for (int i = tid; i < H * BK; i += 256) {
            int m = i >> 4, k = i & 15;
            int gm = m0 + m;
            As[k][m] = (gm < M) ? A[gm * K + k0 + k] : 0.f;
        }
#pragma unroll
        for (int i = tid; i < BK * H; i += 256) {
            int k = i >> 7, n = i & (H - 1);
            Ws[k][n] = W[(k0 + k) * H + n];
        }
        __syncthreads();
#pragma unroll
        for (int k = 0; k < BK; k++) {
            unsigned long long ad[8];
#pragma unroll
            for (int r = 0; r < 8; r++) {
                float av = As[k][ty + r * 16];
                asm("mov.b64 %0, {%1, %1};" : "=l"(ad[r]) : "f"(av));
            }
            unsigned long long wd[4];
#pragma unroll
            for (int c = 0; c < 4; c++) {
                wd[c] = *reinterpret_cast<const unsigned long long*>(&Ws[k][2 * tx + 32 * c]);
            }
#pragma unroll
            for (int r = 0; r < 8; r++)
#pragma unroll
                for (int c = 0; c < 4; c++)
                    asm("fma.rn.f32x2 %0, %1, %2, %0;"
                        : "+l"(acc[r][c]) : "l"(ad[r]), "l"(wd[c]));
        }
        __syncthreads();
    }

#pragma unroll
    for (int r = 0; r < 8; r++) {
        int gm = m0 + ty + r * 16;
        if (gm < M) {
#pragma unroll
            for (int c = 0; c < 4; c++) {
                int n = 2 * tx + 32 * c;
                float lo, hi;
                asm("mov.b64 {%0, %1}, %2;" : "=f"(lo), "=f"(hi) : "l"(acc[r][c]));
                float2 bv = *reinterpret_cast<const float2*>(&bias[n]);
                Z[gm * (H / 2) + (n >> 1)] =
                    __float22half2_rn(make_float2(lo + bv.x, hi + bv.y));
            }
        }
    }
}

// ---------------- hidden GEMM: Z[M,128] = h[M,128](fp16) @ Wh(fp16) + b, WMMA ----
#define AS_LD 40     // halfs per As row (32 + 8 pad)
#define WS_LD 136    // halfs per Ws row (128 + 8 pad)
#define CS_LD 20     // floats per staging row (16 + 4 pad)

__global__ void __launch_bounds__(256)
hgemm_kernel(const __half* __restrict__ A, const __half* __restrict__ Wh,
             const float* __restrict__ bias, __half2* __restrict__ Z, int M)
{
    __shared__ __align__(16) __half As[128 * AS_LD];
    __shared__ __align__(16) __half Ws[32 * WS_LD];
    __shared__ __align__(16) float  Cs[8][16 * CS_LD];
    int tid = threadIdx.x;
    int wid = tid >> 5;
    int lane = tid & 31;
    int m0 = blockIdx.x * 128;

    wmma::fragment<wmma::accumulator, 16, 16, 16, float> acc[8];
#pragma unroll
    for (int nb = 0; nb < 8; nb++) wmma::fill_fragment(acc[nb], 0.0f);

    for (int k0 = 0; k0 < H; k0 += 32) {
#pragma unroll
        for (int i = tid; i < 512; i += 256) {
            int ri = i >> 2, ci = i & 3;
            int gm = m0 + ri;
            uint4 v = make_uint4(0u, 0u, 0u, 0u);
            if (gm < M)
                v = *reinterpret_cast<const uint4*>(A + (size_t)gm * H + k0 + ci * 8);
            *reinterpret_cast<uint4*>(As + ri * AS_LD + ci * 8) = v;
        }
#pragma unroll
        for (int i = tid; i < 512; i += 256) {
            int ri = i >> 4, ci = i & 15;
            uint4 v = *reinterpret_cast<const uint4*>(Wh + (size_t)(k0 + ri) * H + ci * 8);
            *reinterpret_cast<uint4*>(Ws + ri * WS_LD + ci * 8) = v;
        }
        __syncthreads();

#pragma unroll
        for (int ks = 0; ks < 2; ks++) {
            wmma::fragment<wmma::matrix_a, 16, 16, 16, __half, wmma::row_major> af;
            wmma::load_matrix_sync(af, As + (wid * 16) * AS_LD + ks * 16, AS_LD);
#pragma unroll
            for (int nb = 0; nb < 8; nb++) {
                wmma::fragment<wmma::matrix_b, 16, 16, 16, __half, wmma::row_major> bf;
                wmma::load_matrix_sync(bf, Ws + (ks * 16) * WS_LD + nb * 16, WS_LD);
                wmma::mma_sync(acc[nb], af, bf, acc[nb]);
            }
        }
        __syncthreads();
    }

#pragma unroll
    for (int nb = 0; nb < 8; nb++) {
        wmma::store_matrix_sync(&Cs[wid][0], acc[nb], CS_LD, wmma::mem_row_major);
        __syncwarp();
#pragma unroll
        for (int i = lane; i < 128; i += 32) {
            int r = i >> 3, cp = i & 7;
            int gm = m0 + wid * 16 + r;
            if (gm < M) {
                int col = nb * 16 + cp * 2;
                float2 bv = __ldg(reinterpret_cast<const float2*>(&bias[col]));
                float v0 = Cs[wid][r * CS_LD + cp * 2 + 0] + bv.x;
                float v1 = Cs[wid][r * CS_LD + cp * 2 + 1] + bv.y;
                Z[(size_t)gm * (H / 2) + (col >> 1)] =
                    __float22half2_rn(make_float2(v0, v1));
            }
        }
        __syncwarp();
    }
}

// ---------------- aggregation: warp per node, fp16 gathers, unroll-8 ----------
__global__ void __launch_bounds__(256)
agg_leaky_kernel(const uint2* __restrict__ z, uint2* __restrict__ outh)
{
    int node = blockIdx.x * 8 + (threadIdx.x >> 5);
    if (node >= N_NODES) return;
    int lane = threadIdx.x & 31;   // lane owns features [4*lane, 4*lane+4)
    int beg = g_row_ptr[node];
    int end = g_row_ptr[node + 1];

    float4 acc = make_float4(0.f, 0.f, 0.f, 0.f);
    int e = beg;
    for (; e + 8 <= end; e += 8) {
        int2 p[8];
#pragma unroll
        for (int j = 0; j < 8; j++) p[j] = __ldg(&g_csr[e + j]);
        uint2 v[8];
#pragma unroll
        for (int j = 0; j < 8; j++) v[j] = z[p[j].x * 32 + lane];
#pragma unroll
        for (int j = 0; j < 8; j++) {
            float w = __int_as_float(p[j].y);
            float2 a = __half22float2(*(const __half2*)&v[j].x);
            float2 b = __half22float2(*(const __half2*)&v[j].y);
            acc.x += a.x * w; acc.y += a.y * w;
            acc.z += b.x * w; acc.w += b.y * w;
        }
    }
    for (; e + 4 <= end; e += 4) {
        int2 p[4];
#pragma unroll
        for (int j = 0; j < 4; j++) p[j] = __ldg(&g_csr[e + j]);
        uint2 v[4];
#pragma unroll
        for (int j = 0; j < 4; j++) v[j] = z[p[j].x * 32 + lane];
#pragma unroll
        for (int j = 0; j < 4; j++) {
            float w = __int_as_float(p[j].y);
            float2 a = __half22float2(*(const __half2*)&v[j].x);
            float2 b = __half22float2(*(const __half2*)&v[j].y);
            acc.x += a.x * w; acc.y += a.y * w;
            acc.z += b.x * w; acc.w += b.y * w;
        }
    }
    for (; e < end; e++) {
        int2 p = __ldg(&g_csr[e]);
        uint2 v = z[p.x * 32 + lane];
        float w = __int_as_float(p.y);
        float2 a = __half22float2(*(const __half2*)&v.x);
        float2 b = __half22float2(*(const __half2*)&v.y);
        acc.x += a.x * w; acc.y += a.y * w;
        acc.z += b.x * w; acc.w += b.y * w;
    }
    float di = g_deg_inv[node];
    acc.x *= di; acc.y *= di; acc.z *= di; acc.w *= di;
    acc.x = (acc.x > 0.f) ? acc.x : 0.01f * acc.x;
    acc.y = (acc.y > 0.f) ? acc.y : 0.01f * acc.y;
    acc.z = (acc.z > 0.f) ? acc.z : 0.01f * acc.z;
    acc.w = (acc.w > 0.f) ? acc.w : 0.01f * acc.w;
    uint2 o;
    *(__half2*)&o.x = __float22half2_rn(make_float2(acc.x, acc.y));
    *(__half2*)&o.y = __float22half2_rn(make_float2(acc.z, acc.w));
    outh[node * 32 + lane] = o;
}

// ---------------- final FC: out[M,4] = h[M,128](fp16) @ Wfc[128,4] + bfc ----------
__global__ void fc_kernel(const uint2* __restrict__ h2, const float* __restrict__ Wfc,
                          const float* __restrict__ bfc, float* __restrict__ out, int M)
{
    int warp = (blockIdx.x * blockDim.x + threadIdx.x) >> 5;
    int lane = threadIdx.x & 31;
    if (warp >= M) return;
    uint2 v = h2[warp * 32 + lane];           // features 4*lane .. 4*lane+3
    float2 a = __half22float2(*(const __half2*)&v.x);
    float2 b = __half22float2(*(const __half2*)&v.y);
    float hv[4] = {a.x, a.y, b.x, b.y};
    float acc0 = 0.f, acc1 = 0.f, acc2 = 0.f, acc3 = 0.f;
#pragma unroll
    for (int j = 0; j < 4; j++) {
        int k = 4 * lane + j;
        float4 w = __ldg(reinterpret_cast<const float4*>(&Wfc[k * 4]));
        acc0 += hv[j] * w.x;
        acc1 += hv[j] * w.y;
        acc2 += hv[j] * w.z;
        acc3 += hv[j] * w.w;
    }
#pragma unroll
    for (int off = 16; off; off >>= 1) {
        acc0 += __shfl_down_sync(0xffffffffu, acc0, off);
        acc1 += __shfl_down_sync(0xffffffffu, acc1, off);
        acc2 += __shfl_down_sync(0xffffffffu, acc2, off);
        acc3 += __shfl_down_sync(0xffffffffu, acc3, off);
    }
    if (lane == 0) {
        out[warp * 4 + 0] = acc0 + bfc[0];
        out[warp * 4 + 1] = acc1 + bfc[1];
        out[warp * 4 + 2] = acc2 + bfc[2];
        out[warp * 4 + 3] = acc3 + bfc[3];
    }
}

// ---------------- launch ----------------
extern "C" void kernel_launch(void* const* d_in, const int* in_sizes, int n_in,
                              void* d_out, int out_size)
{
    const float* x          = (const float*)d_in[0];
    const int*   edge_index = (const int*)d_in[1];
    const float* edge_attr  = (const float*)d_in[2];
    const float* W_in       = (const float*)d_in[3];
    const float* b_in       = (const float*)d_in[4];
    const float* W_h        = (const float*)d_in[5];
    const float* b_h        = (const float*)d_in[6];
    const float* W_fc       = (const float*)d_in[7];
    const float* b_fc       = (const float*)d_in[8];
    float* out = (float*)d_out;

    const int* src = edge_index;            // row 0
    const int* dst = edge_index + N_EDGES;  // row 1

    __half *bufA, *bufZ, *Wh16;
    cudaGetSymbolAddress((void**)&bufA, g_bufA);
    cudaGetSymbolAddress((void**)&bufZ, g_bufZ);
    cudaGetSymbolAddress((void**)&Wh16, g_Wh16);

    // preprocessing: degree, CSR, weight conversion
    zero_counts_kernel<<<(N_NODES + 255) / 256, 256>>>();
    hist_kernel<<<(N_EDGES + 255) / 256, 256>>>(dst);
    convert_w_kernel<<<(N_HIDDEN * H * H / 4 + 255) / 256, 256>>>(W_h);
    scan1_kernel<<<SCAN_NB, 1024>>>();
    scan2_kernel<<<1, 64>>>();
    scan3_kernel<<<(N_NODES + 255) / 256, 256>>>();
    fill_kernel<<<(N_EDGES + 255) / 256, 256>>>(src, dst, edge_attr);

    const int GEMM_GRID = (N_NODES + H - 1) / H;
    const int AGG_GRID  = (N_NODES + 7) / 8;

    // layer 0: x [N,16] fp32 -> z fp16 -> agg -> h fp16
    gemm_bias_kernel<IN_FEATS><<<GEMM_GRID, 256>>>(x, W_in, b_in, (__half2*)bufZ, N_NODES);
    agg_leaky_kernel<<<AGG_GRID, 256>>>((const uint2*)bufZ, (uint2*)bufA);

    // 19 hidden layers: WMMA GEMM + agg
    for (int l = 0; l < N_HIDDEN; l++) {
        hgemm_kernel<<<GEMM_GRID, 256>>>(bufA, Wh16 + (size_t)l * H * H,
                                         b_h + (size_t)l * H, (__half2*)bufZ, N_NODES);
        agg_leaky_kernel<<<AGG_GRID, 256>>>((const uint2*)bufZ, (uint2*)bufA);
    }

    // final FC: [N,128] fp16 @ [128,4] + b
    const int FC_THREADS = 256;
    const int warps_per_block = FC_THREADS / 32;
    fc_kernel<<<(N_NODES + warps_per_block - 1) / warps_per_block, FC_THREADS>>>(
        (const uint2*)bufA, W_fc, b_fc, out, N_NODES);
}

// round 12
// speedup vs baseline: 1.5557x; 1.5557x over previous
#include <cuda_runtime.h>
#include <cuda_fp16.h>
#include <mma.h>

#define N_NODES 50000
#define N_EDGES 600000
#define IN_FEATS 16
#define H 128
#define N_CLASSES 4
#define N_HIDDEN 19

#define SCAN_NB ((N_NODES + 1023) / 1024)   // 49 blocks of 1024

using namespace nvcuda;

// ---------------- scratch (device globals; no allocation allowed) ----------------
__device__ __half g_bufA[N_NODES * H];          // fp16 h (agg output / GEMM input)
__device__ __half g_bufZ[N_NODES * H];          // fp16 z (GEMM output / agg gather src)
__device__ __half g_Wh16[N_HIDDEN * H * H];     // fp16 hidden weights
__device__ int    g_deg[N_NODES];
__device__ int    g_cnt[N_NODES];
__device__ int    g_row_ptr[N_NODES + 1];
__device__ float  g_deg_inv[N_NODES];
__device__ int    g_bsum[SCAN_NB];
__device__ int    g_boff[SCAN_NB];
__device__ int2   g_csr[N_EDGES];               // {src, float_as_int(w)} per edge

// ---------------- preprocessing ----------------
__global__ void zero_counts_kernel() {
    int i = blockIdx.x * blockDim.x + threadIdx.x;
    if (i < N_NODES) { g_deg[i] = 0; g_cnt[i] = 0; }
}

__global__ void hist_kernel(const int* __restrict__ dst) {
    int i = blockIdx.x * blockDim.x + threadIdx.x;
    if (i < N_EDGES) atomicAdd(&g_deg[dst[i]], 1);
}

__global__ void convert_w_kernel(const float* __restrict__ W) {
    int i = blockIdx.x * blockDim.x + threadIdx.x;     // one float4 -> one uint2(half4)
    if (i < N_HIDDEN * H * H / 4) {
        float4 v = __ldg(reinterpret_cast<const float4*>(W) + i);
        uint2 o;
        *(__half2*)&o.x = __float22half2_rn(make_float2(v.x, v.y));
        *(__half2*)&o.y = __float22half2_rn(make_float2(v.z, v.w));
        reinterpret_cast<uint2*>(g_Wh16)[i] = o;
    }
}

// ---- 3-phase parallel exclusive scan of g_deg -> g_row_ptr ----
__global__ void __launch_bounds__(1024) scan1_kernel() {
    __shared__ int wsum[32];
    int tid = threadIdx.x;
    int i = blockIdx.x * 1024 + tid;
    int lane = tid & 31, wid = tid >> 5;
    int d = (i < N_NODES) ? g_deg[i] : 0;
    int x = d;
#pragma unroll
    for (int off = 1; off < 32; off <<= 1) {
        int t = __shfl_up_sync(0xffffffffu, x, off);
        if (lane >= off) x += t;
    }
    if (lane == 31) wsum[wid] = x;
    __syncthreads();
    if (wid == 0) {
        int s = wsum[lane];
#pragma unroll
        for (int off = 1; off < 32; off <<= 1) {
            int t = __shfl_up_sync(0xffffffffu, s, off);
            if (lane >= off) s += t;
        }
        wsum[lane] = s;
    }
    __syncthreads();
    int base = (wid == 0) ? 0 : wsum[wid - 1];
    int incl = base + x;
    if (i < N_NODES) {
        g_row_ptr[i] = incl - d;                       // block-local exclusive prefix
        g_deg_inv[i] = 1.0f / fmaxf((float)d, 1.0f);
    }
    if (tid == 1023) g_bsum[blockIdx.x] = incl;        // block total
}

__global__ void scan2_kernel() {
    __shared__ int s[64];
    int tid = threadIdx.x;
    s[tid] = (tid < SCAN_NB) ? g_bsum[tid] : 0;
    __syncthreads();
    for (int off = 1; off < 64; off <<= 1) {
        int t = (tid >= off) ? s[tid - off] : 0;
        __syncthreads();
        s[tid] += t;
        __syncthreads();
    }
    if (tid < SCAN_NB) g_boff[tid] = (tid == 0) ? 0 : s[tid - 1];
    if (tid == 63) g_row_ptr[N_NODES] = s[SCAN_NB - 1];
}

__global__ void scan3_kernel() {
    int i = blockIdx.x * blockDim.x + threadIdx.x;
    if (i < N_NODES) g_row_ptr[i] += g_boff[i >> 10];
}

__global__ void fill_kernel(const int* __restrict__ src, const int* __restrict__ dst,
                            const float* __restrict__ ew) {
    int i = blockIdx.x * blockDim.x + threadIdx.x;
    if (i < N_EDGES) {
        int d = dst[i];
        int pos = g_row_ptr[d] + atomicAdd(&g_cnt[d], 1);
        g_csr[pos] = make_int2(src[i], __float_as_int(ew[i]));
    }
}

// ---------------- layer-0 GEMM (fp32 in, FFMA2, fp16 out): K=16 ----------------
template<int K>
__global__ void __launch_bounds__(256)
gemm_bias_kernel(const float* __restrict__ A, const float* __restrict__ W,
                 const float* __restrict__ bias, __half2* __restrict__ Z, int M)
{
    const int BK = 16;
    __shared__ float As[BK][H + 1];
    __shared__ float Ws[BK][H];
    int tid = threadIdx.x;
    int tx = tid & 15;
    int ty = tid >> 4;
    int m0 = blockIdx.x * H;

    unsigned long long acc[8][4];
#pragma unroll
    for (int r = 0; r < 8; r++)
#pragma unroll
        for (int c = 0; c < 4; c++) acc[r][c] = 0ull;

    for (int k0 = 0; k0 < K; k0 += BK) {
#pragma unroll
        for (int i = tid; i < H * BK; i += 256) {
            int m = i >> 4, k = i & 15;
            int gm = m0 + m;
            As[k][m] = (gm < M) ? A[gm * K + k0 + k] : 0.f;
        }
#pragma unroll
        for (int i = tid; i < BK * H; i += 256) {
            int k = i >> 7, n = i & (H - 1);
            Ws[k][n] = W[(k0 + k) * H + n];
        }
        __syncthreads();
#pragma unroll
        for (int k = 0; k < BK; k++) {
            unsigned long long ad[8];
#pragma unroll
            for (int r = 0; r < 8; r++) {
                float av = As[k][ty + r * 16];
                asm("mov.b64 %0, {%1, %1};" : "=l"(ad[r]) : "f"(av));
            }
            unsigned long long wd[4];
#pragma unroll
            for (int c = 0; c < 4; c++) {
                wd[c] = *reinterpret_cast<const unsigned long long*>(&Ws[k][2 * tx + 32 * c]);
            }
#pragma unroll
            for (int r = 0; r < 8; r++)
#pragma unroll
                for (int c = 0; c < 4; c++)
                    asm("fma.rn.f32x2 %0, %1, %2, %0;"
                        : "+l"(acc[r][c]) : "l"(ad[r]), "l"(wd[c]));
        }
        __syncthreads();
    }

#pragma unroll
    for (int r = 0; r < 8; r++) {
        int gm = m0 + ty + r * 16;
        if (gm < M) {
#pragma unroll
            for (int c = 0; c < 4; c++) {
                int n = 2 * tx + 32 * c;
                float lo, hi;
                asm("mov.b64 {%0, %1}, %2;" : "=f"(lo), "=f"(hi) : "l"(acc[r][c]));
                float2 bv = *reinterpret_cast<const float2*>(&bias[n]);
                Z[gm * (H / 2) + (n >> 1)] =
                    __float22half2_rn(make_float2(lo + bv.x, hi + bv.y));
            }
        }
    }
}

// ---------------- hidden GEMM: Z[M,128] = h[M,128](fp16) @ Wh(fp16) + b, WMMA ----
#define AS_LD 40     // halfs per As row (32 + 8 pad)
#define WS_LD 136    // halfs per Ws row (128 + 8 pad)
#define CS_LD 20     // floats per staging row (16 + 4 pad)

__global__ void __launch_bounds__(256)
hgemm_kernel(const __half* __restrict__ A, const __half* __restrict__ Wh,
             const float* __restrict__ bias, __half2* __restrict__ Z, int M)
{
    __shared__ __align__(16) __half As[128 * AS_LD];
    __shared__ __align__(16) __half Ws[32 * WS_LD];
    __shared__ __align__(16) float  Cs[8][16 * CS_LD];
    int tid = threadIdx.x;
    int wid = tid >> 5;
    int lane = tid & 31;
    int m0 = blockIdx.x * 128;

    wmma::fragment<wmma::accumulator, 16, 16, 16, float> acc[8];
#pragma unroll
    for (int nb = 0; nb < 8; nb++) wmma::fill_fragment(acc[nb], 0.0f);

    for (int k0 = 0; k0 < H; k0 += 32) {
#pragma unroll
        for (int i = tid; i < 512; i += 256) {
            int ri = i >> 2, ci = i & 3;
            int gm = m0 + ri;
            uint4 v = make_uint4(0u, 0u, 0u, 0u);
            if (gm < M)
                v = *reinterpret_cast<const uint4*>(A + (size_t)gm * H + k0 + ci * 8);
            *reinterpret_cast<uint4*>(As + ri * AS_LD + ci * 8) = v;
        }
#pragma unroll
        for (int i = tid; i < 512; i += 256) {
            int ri = i >> 4, ci = i & 15;
            uint4 v = *reinterpret_cast<const uint4*>(Wh + (size_t)(k0 + ri) * H + ci * 8);
            *reinterpret_cast<uint4*>(Ws + ri * WS_LD + ci * 8) = v;
        }
        __syncthreads();

#pragma unroll
        for (int ks = 0; ks < 2; ks++) {
            wmma::fragment<wmma::matrix_a, 16, 16, 16, __half, wmma::row_major> af;
            wmma::load_matrix_sync(af, As + (wid * 16) * AS_LD + ks * 16, AS_LD);
#pragma unroll
            for (int nb = 0; nb < 8; nb++) {
                wmma::fragment<wmma::matrix_b, 16, 16, 16, __half, wmma::row_major> bf;
                wmma::load_matrix_sync(bf, Ws + (ks * 16) * WS_LD + nb * 16, WS_LD);
                wmma::mma_sync(acc[nb], af, bf, acc[nb]);
            }
        }
        __syncthreads();
    }

#pragma unroll
    for (int nb = 0; nb < 8; nb++) {
        wmma::store_matrix_sync(&Cs[wid][0], acc[nb], CS_LD, wmma::mem_row_major);
        __syncwarp();
#pragma unroll
        for (int i = lane; i < 128; i += 32) {
            int r = i >> 3, cp = i & 7;
            int gm = m0 + wid * 16 + r;
            if (gm < M) {
                int col = nb * 16 + cp * 2;
                float2 bv = __ldg(reinterpret_cast<const float2*>(&bias[col]));
                float v0 = Cs[wid][r * CS_LD + cp * 2 + 0] + bv.x;
                float v1 = Cs[wid][r * CS_LD + cp * 2 + 1] + bv.y;
                Z[(size_t)gm * (H / 2) + (col >> 1)] =
                    __float22half2_rn(make_float2(v0, v1));
            }
        }
        __syncwarp();
    }
}

// ---------------- aggregation: warp per node, fp16 gathers, unroll-8 ----------
// FUSE_FC=true: skip writing h; apply the final FC (h @ Wfc + bfc) in-register.
template<bool FUSE_FC>
__global__ void __launch_bounds__(256)
agg_leaky_kernel(const uint2* __restrict__ z, uint2* __restrict__ outh,
                 const float* __restrict__ Wfc, const float* __restrict__ bfc,
                 float* __restrict__ out)
{
    int node = blockIdx.x * 8 + (threadIdx.x >> 5);
    if (node >= N_NODES) return;
    int lane = threadIdx.x & 31;   // lane owns features [4*lane, 4*lane+4)
    int beg = g_row_ptr[node];
    int end = g_row_ptr[node + 1];

    float4 acc = make_float4(0.f, 0.f, 0.f, 0.f);
    int e = beg;
    for (; e + 8 <= end; e += 8) {
        int2 p[8];
#pragma unroll
        for (int j = 0; j < 8; j++) p[j] = __ldg(&g_csr[e + j]);
        uint2 v[8];
#pragma unroll
        for (int j = 0; j < 8; j++) v[j] = z[p[j].x * 32 + lane];
#pragma unroll
        for (int j = 0; j < 8; j++) {
            float w = __int_as_float(p[j].y);
            float2 a = __half22float2(*(const __half2*)&v[j].x);
            float2 b = __half22float2(*(const __half2*)&v[j].y);
            acc.x += a.x * w; acc.y += a.y * w;
            acc.z += b.x * w; acc.w += b.y * w;
        }
    }
    for (; e + 4 <= end; e += 4) {
        int2 p[4];
#pragma unroll
        for (int j = 0; j < 4; j++) p[j] = __ldg(&g_csr[e + j]);
        uint2 v[4];
#pragma unroll
        for (int j = 0; j < 4; j++) v[j] = z[p[j].x * 32 + lane];
#pragma unroll
        for (int j = 0; j < 4; j++) {
            float w = __int_as_float(p[j].y);
            float2 a = __half22float2(*(const __half2*)&v[j].x);
            float2 b = __half22float2(*(const __half2*)&v[j].y);
            acc.x += a.x * w; acc.y += a.y * w;
            acc.z += b.x * w; acc.w += b.y * w;
        }
    }
    for (; e < end; e++) {
        int2 p = __ldg(&g_csr[e]);
        uint2 v = z[p.x * 32 + lane];
        float w = __int_as_float(p.y);
        float2 a = __half22float2(*(const __half2*)&v.x);
        float2 b = __half22float2(*(const __half2*)&v.y);
        acc.x += a.x * w; acc.y += a.y * w;
        acc.z += b.x * w; acc.w += b.y * w;
    }
    float di = g_deg_inv[node];
    acc.x *= di; acc.y *= di; acc.z *= di; acc.w *= di;
    acc.x = (acc.x > 0.f) ? acc.x : 0.01f * acc.x;
    acc.y = (acc.y > 0.f) ? acc.y : 0.01f * acc.y;
    acc.z = (acc.z > 0.f) ? acc.z : 0.01f * acc.z;
    acc.w = (acc.w > 0.f) ? acc.w : 0.01f * acc.w;

    if (!FUSE_FC) {
        uint2 o;
        *(__half2*)&o.x = __float22half2_rn(make_float2(acc.x, acc.y));
        *(__half2*)&o.y = __float22half2_rn(make_float2(acc.z, acc.w));
        outh[node * 32 + lane] = o;
    } else {
        // match the unfused numerics: h goes through fp16 before the FC
        __half2 hx = __float22half2_rn(make_float2(acc.x, acc.y));
        __half2 hy = __float22half2_rn(make_float2(acc.z, acc.w));
        float2 fa = __half22float2(hx);
        float2 fb = __half22float2(hy);
        float hv[4] = {fa.x, fa.y, fb.x, fb.y};
        float a0 = 0.f, a1 = 0.f, a2 = 0.f, a3 = 0.f;
#pragma unroll
        for (int j = 0; j < 4; j++) {
            int k = 4 * lane + j;
            float4 w = __ldg(reinterpret_cast<const float4*>(&Wfc[k * 4]));
            a0 += hv[j] * w.x;
            a1 += hv[j] * w.y;
            a2 += hv[j] * w.z;
            a3 += hv[j] * w.w;
        }
#pragma unroll
        for (int off = 16; off; off >>= 1) {
            a0 += __shfl_down_sync(0xffffffffu, a0, off);
            a1 += __shfl_down_sync(0xffffffffu, a1, off);
            a2 += __shfl_down_sync(0xffffffffu, a2, off);
            a3 += __shfl_down_sync(0xffffffffu, a3, off);
        }
        if (lane == 0) {
            out[node * 4 + 0] = a0 + bfc[0];
            out[node * 4 + 1] = a1 + bfc[1];
            out[node * 4 + 2] = a2 + bfc[2];
            out[node * 4 + 3] = a3 + bfc[3];
        }
    }
}

// ---------------- launch ----------------
extern "C" void kernel_launch(void* const* d_in, const int* in_sizes, int n_in,
                              void* d_out, int out_size)
{
    const float* x          = (const float*)d_in[0];
    const int*   edge_index = (const int*)d_in[1];
    const float* edge_attr  = (const float*)d_in[2];
    const float* W_in       = (const float*)d_in[3];
    const float* b_in       = (const float*)d_in[4];
    const float* W_h        = (const float*)d_in[5];
    const float* b_h        = (const float*)d_in[6];
    const float* W_fc       = (const float*)d_in[7];
    const float* b_fc       = (const float*)d_in[8];
    float* out = (float*)d_out;

    const int* src = edge_index;            // row 0
    const int* dst = edge_index + N_EDGES;  // row 1

    __half *bufA, *bufZ, *Wh16;
    cudaGetSymbolAddress((void**)&bufA, g_bufA);
    cudaGetSymbolAddress((void**)&bufZ, g_bufZ);
    cudaGetSymbolAddress((void**)&Wh16, g_Wh16);

    // preprocessing: degree, CSR, weight conversion
    zero_counts_kernel<<<(N_NODES + 255) / 256, 256>>>();
    hist_kernel<<<(N_EDGES + 255) / 256, 256>>>(dst);
    convert_w_kernel<<<(N_HIDDEN * H * H / 4 + 255) / 256, 256>>>(W_h);
    scan1_kernel<<<SCAN_NB, 1024>>>();
    scan2_kernel<<<1, 64>>>();
    scan3_kernel<<<(N_NODES + 255) / 256, 256>>>();
    fill_kernel<<<(N_EDGES + 255) / 256, 256>>>(src, dst, edge_attr);

    const int GEMM_GRID = (N_NODES + H - 1) / H;
    const int AGG_GRID  = (N_NODES + 7) / 8;

    // layer 0: x [N,16] fp32 -> z fp16 -> agg -> h fp16
    gemm_bias_kernel<IN_FEATS><<<GEMM_GRID, 256>>>(x, W_in, b_in, (__half2*)bufZ, N_NODES);
    agg_leaky_kernel<false><<<AGG_GRID, 256>>>((const uint2*)bufZ, (uint2*)bufA,
                                               nullptr, nullptr, nullptr);

    // 19 hidden layers: WMMA GEMM + agg; last agg fuses the FC
    for (int l = 0; l < N_HIDDEN; l++) {
        hgemm_kernel<<<GEMM_GRID, 256>>>(bufA, Wh16 + (size_t)l * H * H,
                                         b_h + (size_t)l * H, (__half2*)bufZ, N_NODES);
        if (l < N_HIDDEN - 1) {
            agg_leaky_kernel<false><<<AGG_GRID, 256>>>((const uint2*)bufZ, (uint2*)bufA,
                                                       nullptr, nullptr, nullptr);
        } else {
            agg_leaky_kernel<true><<<AGG_GRID, 256>>>((const uint2*)bufZ, nullptr,
                                                      W_fc, b_fc, out);
        }
    }
}